// round 1
// baseline (speedup 1.0000x reference)
#include <cuda_runtime.h>
#include <cuda_bf16.h>
#include <math_constants.h>

// LocalWindowAttention: B=2, S=4096, D=1024, H=16, hd=64, W=16 (lp=8, rp=7)
// out = softmax_window( (xWq^T)(xWk^T)^T / 8 ) (xWv^T)  @ Wo^T
//
// Round 1 baseline: fp32 SIMT tiled GEMMs + warp-per-(b,s,h) windowed attention.

#define B_  2
#define S_  4096
#define D_  1024
#define H_  16
#define HD_ 64
#define W_  16
#define LP_ 8
#define M_  (B_ * S_)          // 8192 rows

// ---------------- scratch (static device globals; no allocation allowed) ----
__device__ float g_q[M_ * D_];
__device__ float g_k[M_ * D_];
__device__ float g_v[M_ * D_];
__device__ float g_attn[M_ * D_];

// ---------------- GEMM: C[M,N] = A[M,K] * B[N,K]^T  (both row-major) --------
#define TM 128
#define TN 128
#define TK 16

__global__ __launch_bounds__(256, 2)
void gemm_nt_kernel(const float* __restrict__ A,
                    const float* __restrict__ Bm,
                    float* __restrict__ C,
                    int M, int N, int K)
{
    __shared__ float As[TK][TM + 4];
    __shared__ float Bs[TK][TN + 4];

    const int tid = threadIdx.x;           // 256 threads
    const int bm  = blockIdx.y * TM;
    const int bn  = blockIdx.x * TN;
    const int tx  = tid & 15;              // n-direction (8 cols each)
    const int ty  = tid >> 4;              // m-direction (8 rows each)

    float acc[8][8];
#pragma unroll
    for (int i = 0; i < 8; i++)
#pragma unroll
        for (int j = 0; j < 8; j++) acc[i][j] = 0.f;

    const int lr = tid >> 2;               // 0..63  (row within 64-row half)
    const int lc = (tid & 3) * 4;          // 0,4,8,12 (k offset)

    for (int k0 = 0; k0 < K; k0 += TK) {
#pragma unroll
        for (int p = 0; p < 2; p++) {
            const int r = lr + p * 64;
            float4 va = *(const float4*)(A  + (size_t)(bm + r) * K + k0 + lc);
            As[lc + 0][r] = va.x; As[lc + 1][r] = va.y;
            As[lc + 2][r] = va.z; As[lc + 3][r] = va.w;
            float4 vb = *(const float4*)(Bm + (size_t)(bn + r) * K + k0 + lc);
            Bs[lc + 0][r] = vb.x; Bs[lc + 1][r] = vb.y;
            Bs[lc + 2][r] = vb.z; Bs[lc + 3][r] = vb.w;
        }
        __syncthreads();

#pragma unroll
        for (int kk = 0; kk < TK; kk++) {
            float a[8], b[8];
#pragma unroll
            for (int i = 0; i < 8; i++) a[i] = As[kk][ty * 8 + i];
#pragma unroll
            for (int j = 0; j < 8; j++) b[j] = Bs[kk][tx * 8 + j];
#pragma unroll
            for (int i = 0; i < 8; i++)
#pragma unroll
                for (int j = 0; j < 8; j++) acc[i][j] += a[i] * b[j];
        }
        __syncthreads();
    }

#pragma unroll
    for (int i = 0; i < 8; i++) {
        float* crow = C + (size_t)(bm + ty * 8 + i) * N + bn + tx * 8;
#pragma unroll
        for (int j = 0; j < 8; j += 4) {
            float4 v = make_float4(acc[i][j], acc[i][j+1], acc[i][j+2], acc[i][j+3]);
            *(float4*)(crow + j) = v;
        }
    }
}

// ---------------- windowed attention: one warp per (b, s, h) ----------------
__global__ __launch_bounds__(256)
void attn_kernel(const float* __restrict__ q,
                 const float* __restrict__ k,
                 const float* __restrict__ v,
                 float* __restrict__ o)
{
    const int gwarp = (blockIdx.x * blockDim.x + threadIdx.x) >> 5;
    const int lane  = threadIdx.x & 31;
    // gwarp -> (b, s, h), h fastest
    const int h = gwarp & (H_ - 1);
    const int s = (gwarp >> 4) & (S_ - 1);
    const int b = gwarp >> 16;             // 4096*16 = 65536 warps per batch

    const size_t rowbase = (size_t)(b * S_ + s) * D_ + h * HD_;
    const float q0 = q[rowbase + lane];
    const float q1 = q[rowbase + lane + 32];

    float sc[W_];
#pragma unroll
    for (int w = 0; w < W_; w++) {
        const int pos = s + w - LP_;
        float r = -CUDART_INF_F;
        if (pos >= 0 && pos < S_) {
            const size_t kb = (size_t)(b * S_ + pos) * D_ + h * HD_;
            float part = q0 * k[kb + lane] + q1 * k[kb + lane + 32];
#pragma unroll
            for (int off = 16; off > 0; off >>= 1)
                part += __shfl_xor_sync(0xFFFFFFFFu, part, off);
            r = part * 0.125f;             // 1/sqrt(64)
        }
        sc[w] = r;
    }

    float m = sc[0];
#pragma unroll
    for (int w = 1; w < W_; w++) m = fmaxf(m, sc[w]);

    float denom = 0.f, p[W_];
#pragma unroll
    for (int w = 0; w < W_; w++) { p[w] = __expf(sc[w] - m); denom += p[w]; }
    const float inv = 1.f / denom;

    float o0 = 0.f, o1 = 0.f;
#pragma unroll
    for (int w = 0; w < W_; w++) {
        const int pos = s + w - LP_;
        if (pos >= 0 && pos < S_) {
            const size_t vb = (size_t)(b * S_ + pos) * D_ + h * HD_;
            o0 += p[w] * v[vb + lane];
            o1 += p[w] * v[vb + lane + 32];
        }
    }
    o[rowbase + lane]      = o0 * inv;
    o[rowbase + lane + 32] = o1 * inv;
}

// ---------------- launch -----------------------------------------------------
extern "C" void kernel_launch(void* const* d_in, const int* in_sizes, int n_in,
                              void* d_out, int out_size)
{
    const float* x  = (const float*)d_in[0];
    const float* Wq = (const float*)d_in[1];
    const float* Wk = (const float*)d_in[2];
    const float* Wv = (const float*)d_in[3];
    const float* Wo = (const float*)d_in[4];
    float* out = (float*)d_out;

    float *qp, *kp, *vp, *ap;
    cudaGetSymbolAddress((void**)&qp, g_q);
    cudaGetSymbolAddress((void**)&kp, g_k);
    cudaGetSymbolAddress((void**)&vp, g_v);
    cudaGetSymbolAddress((void**)&ap, g_attn);

    dim3 ggrid(D_ / TN, M_ / TM);          // (8, 64)
    gemm_nt_kernel<<<ggrid, 256>>>(x, Wq, qp, M_, D_, D_);
    gemm_nt_kernel<<<ggrid, 256>>>(x, Wk, kp, M_, D_, D_);
    gemm_nt_kernel<<<ggrid, 256>>>(x, Wv, vp, M_, D_, D_);

    const int nwarps = B_ * S_ * H_;       // 131072
    attn_kernel<<<nwarps * 32 / 256, 256>>>(qp, kp, vp, ap);

    gemm_nt_kernel<<<ggrid, 256>>>(ap, Wo, out, M_, D_, D_);
}

// round 4
// speedup vs baseline: 2.3662x; 2.3662x over previous
#include <cuda_runtime.h>
#include <cuda_bf16.h>
#include <math_constants.h>
#include <cstdint>

// LocalWindowAttention: B=2, S=4096, D=1024, H=16, hd=64, W=16 (lp=8)
// Round 4: mma.sync bf16 3-pass (hi/lo split) GEMMs (sm_100-safe), fused QKV.

#define B_  2
#define S_  4096
#define D_  1024
#define H_  16
#define HD_ 64
#define W_  16
#define LP_ 8
#define M_  (B_ * S_)
#define K_  1024

// ---------------- scratch (static device globals) ---------------------------
__device__ float g_qkv[3 * M_ * D_];          // q, k, v contiguous
__device__ __nv_bfloat16 g_xh[M_ * D_];
__device__ __nv_bfloat16 g_xl[M_ * D_];
__device__ __nv_bfloat16 g_wh[4 * D_ * D_];   // Wq,Wk,Wv,Wo hi
__device__ __nv_bfloat16 g_wl[4 * D_ * D_];   // lo
__device__ __nv_bfloat16 g_ah[M_ * D_];
__device__ __nv_bfloat16 g_al[M_ * D_];

// ---------------- helpers -----------------------------------------------------
#define SW128(o) ((o) ^ (((o) >> 3) & 0x70))

#define CP16(dst, src) \
    asm volatile("cp.async.cg.shared.global [%0], [%1], 16;" :: "r"(dst), "l"(src) : "memory")
#define CP_COMMIT() asm volatile("cp.async.commit_group;" ::: "memory")
#define CP_WAIT(n)  asm volatile("cp.async.wait_group %0;" :: "n"(n) : "memory")

__device__ __forceinline__ void ldsm4(uint32_t r[4], uint32_t addr) {
    asm volatile("ldmatrix.sync.aligned.m8n8.x4.shared.b16 {%0,%1,%2,%3}, [%4];"
                 : "=r"(r[0]), "=r"(r[1]), "=r"(r[2]), "=r"(r[3]) : "r"(addr));
}

__device__ __forceinline__ void mma16816(float* c, const uint32_t a[4],
                                         uint32_t b0, uint32_t b1) {
    asm volatile(
        "mma.sync.aligned.m16n8k16.row.col.f32.bf16.bf16.f32 "
        "{%0,%1,%2,%3}, {%4,%5,%6,%7}, {%8,%9}, {%0,%1,%2,%3};"
        : "+f"(c[0]), "+f"(c[1]), "+f"(c[2]), "+f"(c[3])
        : "r"(a[0]), "r"(a[1]), "r"(a[2]), "r"(a[3]), "r"(b0), "r"(b1));
}

// ---------------- convert: fp32 -> (bf16 hi, bf16 lo) -----------------------
__global__ void convert_kernel(const float* __restrict__ src,
                               __nv_bfloat16* __restrict__ hi,
                               __nv_bfloat16* __restrict__ lo, int n4)
{
    int i = blockIdx.x * blockDim.x + threadIdx.x;
    if (i >= n4) return;
    float4 v = ((const float4*)src)[i];
    __nv_bfloat16 h0 = __float2bfloat16(v.x);
    __nv_bfloat16 h1 = __float2bfloat16(v.y);
    __nv_bfloat16 h2 = __float2bfloat16(v.z);
    __nv_bfloat16 h3 = __float2bfloat16(v.w);
    __nv_bfloat16 l0 = __float2bfloat16(v.x - __bfloat162float(h0));
    __nv_bfloat16 l1 = __float2bfloat16(v.y - __bfloat162float(h1));
    __nv_bfloat16 l2 = __float2bfloat16(v.z - __bfloat162float(h2));
    __nv_bfloat16 l3 = __float2bfloat16(v.w - __bfloat162float(h3));
    ((__nv_bfloat162*)hi)[2 * i]     = __halves2bfloat162(h0, h1);
    ((__nv_bfloat162*)hi)[2 * i + 1] = __halves2bfloat162(h2, h3);
    ((__nv_bfloat162*)lo)[2 * i]     = __halves2bfloat162(l0, l1);
    ((__nv_bfloat162*)lo)[2 * i + 1] = __halves2bfloat162(l2, l3);
}

// ---------------- mma.sync GEMM ----------------------------------------------
// C_chunk[M,1024] = A[M,1024] * B[Ntot,1024]^T ; bn>>10 selects output chunk.
#define TILE_M 128
#define TILE_N 256
#define KC     64                 // bf16 per chunk (128 B / smem row)
#define NCHUNK (K_ / KC)          // 16
#define ATILE_B (TILE_M * 128)    // 16384
#define BTILE_B (TILE_N * 128)    // 32768
#define STAGE_B (2 * ATILE_B + 2 * BTILE_B)   // 98304
#define SMEM_TOTAL (2 * STAGE_B)              // 196608

__global__ __launch_bounds__(256, 1)
void gemm_mma(const __nv_bfloat16* __restrict__ Ah, const __nv_bfloat16* __restrict__ Al,
              const __nv_bfloat16* __restrict__ Bh, const __nv_bfloat16* __restrict__ Bl,
              float* __restrict__ C, size_t out_chunk)
{
    extern __shared__ char smem[];
    const uint32_t sbase = (uint32_t)__cvta_generic_to_shared(smem);
    const int tid  = threadIdx.x;
    const int wid  = tid >> 5;
    const int lane = tid & 31;
    const int bm = blockIdx.y * TILE_M;
    const int bn = blockIdx.x * TILE_N;
    const int wm = wid >> 1;              // 0..3  (m32 slice)
    const int wn = wid & 1;               // 0..1  (n128 slice)

    // ---- loader: 24 cp.asyncs of 16B per thread per chunk ----
    auto load_chunk = [&](int ch) {
        const uint32_t st = sbase + (ch & 1) * STAGE_B;
        const int k0 = ch * KC;
#pragma unroll
        for (int i = 0; i < 4; i++) {            // A: 128 rows x 8 x 16B
            int idx = tid + i * 256;
            int row = idx >> 3, c = idx & 7;
            uint32_t off = SW128((uint32_t)(row * 128 + c * 16));
            CP16(st + off,            Ah + (size_t)(bm + row) * K_ + k0 + c * 8);
            CP16(st + ATILE_B + off,  Al + (size_t)(bm + row) * K_ + k0 + c * 8);
        }
#pragma unroll
        for (int i = 0; i < 8; i++) {            // B: 256 rows x 8 x 16B
            int idx = tid + i * 256;
            int row = idx >> 3, c = idx & 7;
            uint32_t off = SW128((uint32_t)(row * 128 + c * 16));
            CP16(st + 2 * ATILE_B + off,           Bh + (size_t)(bn + row) * K_ + k0 + c * 8);
            CP16(st + 2 * ATILE_B + BTILE_B + off, Bl + (size_t)(bn + row) * K_ + k0 + c * 8);
        }
        CP_COMMIT();
    };

    // per-lane ldmatrix address components (SW128 => granule ^= row&7)
    const int lr7   = lane & 7;
    const int q     = lane >> 3;
    const int rowadd = (q & 1) * 8 + lr7;
    const int qh    = q >> 1;

    float acc[128];
#pragma unroll
    for (int i = 0; i < 128; i++) acc[i] = 0.f;

    load_chunk(0);
    for (int ch = 0; ch < NCHUNK; ch++) {
        if (ch + 1 < NCHUNK) { load_chunk(ch + 1); CP_WAIT(1); }
        else                 { CP_WAIT(0); }
        __syncthreads();

        const uint32_t st   = sbase + (ch & 1) * STAGE_B;
        const uint32_t stAh = st;
        const uint32_t stAl = st + ATILE_B;
        const uint32_t stBh = st + 2 * ATILE_B;
        const uint32_t stBl = st + 2 * ATILE_B + BTILE_B;

#pragma unroll
        for (int ks = 0; ks < 4; ks++) {
            const uint32_t gsw = (uint32_t)(((ks * 2 + qh) ^ lr7) * 16);

            uint32_t aH[2][4], aL[2][4];
#pragma unroll
            for (int mi = 0; mi < 2; mi++) {
                uint32_t ro = (uint32_t)((wm * 32 + mi * 16 + rowadd) * 128);
                ldsm4(aH[mi], stAh + ro + gsw);
                ldsm4(aL[mi], stAl + ro + gsw);
            }
#pragma unroll
            for (int j = 0; j < 8; j++) {
                uint32_t ro = (uint32_t)((wn * 128 + j * 16 + rowadd) * 128);
                uint32_t bH[4], bL[4];
                ldsm4(bH, stBh + ro + gsw);
                ldsm4(bL, stBl + ro + gsw);
#pragma unroll
                for (int mi = 0; mi < 2; mi++) {
                    float* c0 = &acc[(mi * 16 + 2 * j) * 4];
                    float* c1 = &acc[(mi * 16 + 2 * j + 1) * 4];
                    mma16816(c0, aH[mi], bH[0], bH[2]);   // Ah*Bh
                    mma16816(c1, aH[mi], bH[1], bH[3]);
                    mma16816(c0, aH[mi], bL[0], bL[2]);   // Ah*Bl
                    mma16816(c1, aH[mi], bL[1], bL[3]);
                    mma16816(c0, aL[mi], bH[0], bH[2]);   // Al*Bh
                    mma16816(c1, aL[mi], bH[1], bH[3]);
                }
            }
        }
        __syncthreads();
    }

    // ---- epilogue: direct fp32 stores ----
    float* Cout = C + (size_t)(bn >> 10) * out_chunk;
    const int bcol = (bn & 1023) + wn * 128 + (lane & 3) * 2;
    const int brow = bm + wm * 32 + (lane >> 2);
#pragma unroll
    for (int mi = 0; mi < 2; mi++) {
#pragma unroll
        for (int n8 = 0; n8 < 16; n8++) {
            const float* a = &acc[(mi * 16 + n8) * 4];
            const int row = brow + mi * 16;
            const int col = bcol + n8 * 8;
            *(float2*)(Cout + (size_t)row * D_ + col)       = make_float2(a[0], a[1]);
            *(float2*)(Cout + (size_t)(row + 8) * D_ + col) = make_float2(a[2], a[3]);
        }
    }
}

// ---------------- windowed attention: one warp per (b, s, h) ----------------
__global__ __launch_bounds__(256)
void attn_kernel(const float* __restrict__ q,
                 const float* __restrict__ k,
                 const float* __restrict__ v)
{
    const int gwarp = (blockIdx.x * blockDim.x + threadIdx.x) >> 5;
    const int lane  = threadIdx.x & 31;
    const int h = gwarp & (H_ - 1);
    const int s = (gwarp >> 4) & (S_ - 1);
    const int b = gwarp >> 16;

    const size_t rowbase = (size_t)(b * S_ + s) * D_ + h * HD_;
    const float q0 = q[rowbase + lane];
    const float q1 = q[rowbase + lane + 32];

    float sc[W_];
#pragma unroll
    for (int w = 0; w < W_; w++) {
        const int pos = s + w - LP_;
        float r = -CUDART_INF_F;
        if (pos >= 0 && pos < S_) {
            const size_t kb = (size_t)(b * S_ + pos) * D_ + h * HD_;
            float part = q0 * k[kb + lane] + q1 * k[kb + lane + 32];
#pragma unroll
            for (int off = 16; off > 0; off >>= 1)
                part += __shfl_xor_sync(0xFFFFFFFFu, part, off);
            r = part * 0.125f;
        }
        sc[w] = r;
    }

    float m = sc[0];
#pragma unroll
    for (int w = 1; w < W_; w++) m = fmaxf(m, sc[w]);

    float denom = 0.f, p[W_];
#pragma unroll
    for (int w = 0; w < W_; w++) { p[w] = __expf(sc[w] - m); denom += p[w]; }
    const float inv = 1.f / denom;

    float o0 = 0.f, o1 = 0.f;
#pragma unroll
    for (int w = 0; w < W_; w++) {
        const int pos = s + w - LP_;
        if (pos >= 0 && pos < S_) {
            const size_t vb = (size_t)(b * S_ + pos) * D_ + h * HD_;
            o0 += p[w] * v[vb + lane];
            o1 += p[w] * v[vb + lane + 32];
        }
    }
    const float v0 = o0 * inv, v1 = o1 * inv;
    const __nv_bfloat16 h0 = __float2bfloat16(v0);
    const __nv_bfloat16 h1 = __float2bfloat16(v1);
    g_ah[rowbase + lane]      = h0;
    g_ah[rowbase + lane + 32] = h1;
    g_al[rowbase + lane]      = __float2bfloat16(v0 - __bfloat162float(h0));
    g_al[rowbase + lane + 32] = __float2bfloat16(v1 - __bfloat162float(h1));
}

// ---------------- launch -----------------------------------------------------
extern "C" void kernel_launch(void* const* d_in, const int* in_sizes, int n_in,
                              void* d_out, int out_size)
{
    const float* x  = (const float*)d_in[0];
    const float* Wq = (const float*)d_in[1];
    const float* Wk = (const float*)d_in[2];
    const float* Wv = (const float*)d_in[3];
    const float* Wo = (const float*)d_in[4];
    float* out = (float*)d_out;

    float* qkv;
    __nv_bfloat16 *xh, *xl, *wh, *wl, *ah, *al;
    cudaGetSymbolAddress((void**)&qkv, g_qkv);
    cudaGetSymbolAddress((void**)&xh, g_xh);
    cudaGetSymbolAddress((void**)&xl, g_xl);
    cudaGetSymbolAddress((void**)&wh, g_wh);
    cudaGetSymbolAddress((void**)&wl, g_wl);
    cudaGetSymbolAddress((void**)&ah, g_ah);
    cudaGetSymbolAddress((void**)&al, g_al);

    cudaFuncSetAttribute(gemm_mma, cudaFuncAttributeMaxDynamicSharedMemorySize, SMEM_TOTAL);

    // 1) fp32 -> bf16 hi/lo splits
    const int n4x = M_ * D_ / 4;
    convert_kernel<<<(n4x + 255) / 256, 256>>>(x, xh, xl, n4x);
    const int n4w = D_ * D_ / 4;
    convert_kernel<<<(n4w + 255) / 256, 256>>>(Wq, wh + 0 * D_ * D_, wl + 0 * D_ * D_, n4w);
    convert_kernel<<<(n4w + 255) / 256, 256>>>(Wk, wh + 1 * D_ * D_, wl + 1 * D_ * D_, n4w);
    convert_kernel<<<(n4w + 255) / 256, 256>>>(Wv, wh + 2 * D_ * D_, wl + 2 * D_ * D_, n4w);
    convert_kernel<<<(n4w + 255) / 256, 256>>>(Wo, wh + 3 * D_ * D_, wl + 3 * D_ * D_, n4w);

    // 2) fused Q/K/V projection: B = [3072, 1024] (Wq|Wk|Wv stacked)
    dim3 qkvgrid(3 * D_ / TILE_N, M_ / TILE_M);   // (12, 64)
    gemm_mma<<<qkvgrid, 256, SMEM_TOTAL>>>(xh, xl, wh, wl, qkv, (size_t)M_ * D_);

    // 3) windowed attention (emits bf16 hi/lo directly)
    const float* qp = qkv;
    const float* kp = qkv + (size_t)M_ * D_;
    const float* vp = qkv + 2 * (size_t)M_ * D_;
    const int nwarps = B_ * S_ * H_;
    attn_kernel<<<nwarps * 32 / 256, 256>>>(qp, kp, vp);

    // 4) output projection
    dim3 ogrid(D_ / TILE_N, M_ / TILE_M);         // (4, 64)
    gemm_mma<<<ogrid, 256, SMEM_TOTAL>>>(ah, al, wh + 3 * D_ * D_, wl + 3 * D_ * D_,
                                         out, (size_t)M_ * D_);
}